// round 14
// baseline (speedup 1.0000x reference)
#include <cuda_runtime.h>
#include <cuda_fp16.h>
#include <cstdint>

// InstantNGPMLP fused on mma.sync m16n8k16 (tcgen05 unavailable under the
// harness's compute_103 virtual arch).
// R14 vs R13 (77.9us, L1=61.4% weight-LDS-bound, tensor=50.9%):
//   - M=64 rows/warp (4 subtiles): one B-frag LDS feeds 8 mma (was 2/4) ->
//     weight smem bytes per row halved again.
//   - zero-C mma form for ks=0 kills ~416 accumulator-init MOVs per tile.
//   - B frag loaded per-j (not banked): live regs ~210 < 255 cap, (128,2),
//     8 warps/SM. Per-ks burst = 32 independent mma -> high per-warp duty.
//   - raw-x prefetch dropped (reg budget); x latency amortized over 4x work.
//   - pure fp16 operands (rel_err 2.984e-4, 3.3x margin).

#define THREADS 128
#define WARPS 4
#define NROWS 1048576
#define WTILES (NROWS / 64)   // 16384 warp-tiles of 64 rows
#define GRID 296              // 2 CTAs/SM * 148

__device__ __forceinline__ void mma16816(float d[4], const uint32_t* a, uint32_t b0, uint32_t b1) {
    asm volatile(
        "mma.sync.aligned.m16n8k16.row.col.f32.f16.f16.f32 "
        "{%0,%1,%2,%3}, {%4,%5,%6,%7}, {%8,%9}, {%0,%1,%2,%3};"
        : "+f"(d[0]), "+f"(d[1]), "+f"(d[2]), "+f"(d[3])
        : "r"(a[0]), "r"(a[1]), "r"(a[2]), "r"(a[3]), "r"(b0), "r"(b1));
}
// Zero-C form: d = A*B (no pre-init of accumulators needed).
__device__ __forceinline__ void mma16816_z(float d[4], const uint32_t* a, uint32_t b0, uint32_t b1) {
    asm volatile(
        "mma.sync.aligned.m16n8k16.row.col.f32.f16.f16.f32 "
        "{%0,%1,%2,%3}, {%4,%5,%6,%7}, {%8,%9}, {%10,%10,%10,%10};"
        : "=f"(d[0]), "=f"(d[1]), "=f"(d[2]), "=f"(d[3])
        : "r"(a[0]), "r"(a[1]), "r"(a[2]), "r"(a[3]), "r"(b0), "r"(b1), "f"(0.0f));
}

__device__ __forceinline__ uint32_t pack_h(float f0, float f1) {
    __half2 h = __floats2half2_rn(f0, f1);
    return *reinterpret_cast<uint32_t*>(&h);
}

// ---- smem: fp16 B fragments (~22KB) + biases ----
__shared__ uint2 sf1[512];    // L1: 2ks x 8nf x 32 lanes
__shared__ uint2 sf2[1024];   // L2: 4ks x 8nf x 32
__shared__ uint2 sf3[1024];   // L3
__shared__ uint2 sf4[256];    // L4: 4ks x 2nf x 32
__shared__ float sb1[64], sb2[64], sb3[64], sb4[16];

__device__ void stage(const float* __restrict__ W, int K, int N,
                      uint2* __restrict__ frag, int tid) {
    const int NF = N / 8, total = (K / 16) * NF * 32;
    for (int idx = tid; idx < total; idx += THREADS) {
        int lane = idx & 31, f = idx >> 5;
        int j = f % NF, ks = f / NF;
        int g = lane >> 2, t = lane & 3;
        int n = j * 8 + g;
        int k0 = ks * 16 + 2 * t;
        frag[idx] = make_uint2(pack_h(W[k0 * N + n],       W[(k0 + 1) * N + n]),
                               pack_h(W[(k0 + 8) * N + n], W[(k0 + 9) * N + n]));
    }
}

// Four-subtile layer: one B-frag load feeds 4 mma (one per subtile);
// per k-step the 32-mma burst is fully independent.
template <int KS, int NF>
__device__ __forceinline__ void layer_mma4(float (&d)[4][NF][4],
                                           const uint2* __restrict__ frag,
                                           const uint32_t (&A)[4][16], int lane) {
#pragma unroll
    for (int ks = 0; ks < KS; ks++) {
#pragma unroll
        for (int j = 0; j < NF; j++) {
            uint2 b = frag[(ks * NF + j) * 32 + lane];
            if (ks == 0) {
#pragma unroll
                for (int st = 0; st < 4; st++) mma16816_z(d[st][j], &A[st][0], b.x, b.y);
            } else {
#pragma unroll
                for (int st = 0; st < 4; st++) mma16816(d[st][j], &A[st][ks * 4], b.x, b.y);
            }
        }
    }
}

// Epilogue: bias + relu + fp16 pack (one subtile).
__device__ __forceinline__ void epi_relu(const float (&d)[8][4],
                                         const float* __restrict__ bias, int lane,
                                         uint32_t* __restrict__ Ah) {
    int t = lane & 3;
#pragma unroll
    for (int ks = 0; ks < 4; ks++) {
#pragma unroll
        for (int h = 0; h < 2; h++) {
            int j = 2 * ks + h;
            float2 b = *(const float2*)&bias[j * 8 + 2 * t];
            float f0 = fmaxf(d[j][0] + b.x, 0.0f);
            float f1 = fmaxf(d[j][1] + b.y, 0.0f);
            float f2 = fmaxf(d[j][2] + b.x, 0.0f);
            float f3 = fmaxf(d[j][3] + b.y, 0.0f);
            Ah[ks * 4 + h * 2 + 0] = pack_h(f0, f1);
            Ah[ks * 4 + h * 2 + 1] = pack_h(f2, f3);
        }
    }
}

__global__ void __launch_bounds__(THREADS, 2)
mlp_hmma_kernel(const float* __restrict__ x,
                const float* __restrict__ Wi, const float* __restrict__ bi,
                const float* __restrict__ W1, const float* __restrict__ b1,
                const float* __restrict__ W2, const float* __restrict__ b2,
                const float* __restrict__ Wo, const float* __restrict__ bo,
                float* __restrict__ out) {
    const int tid = threadIdx.x;
    const int wid = tid >> 5;
    const int lane = tid & 31;
    const int g = lane >> 2, t = lane & 3;

    stage(Wi, 32, 64, sf1, tid);
    stage(W1, 64, 64, sf2, tid);
    stage(W2, 64, 64, sf3, tid);
    stage(Wo, 64, 16, sf4, tid);
    for (int i = tid; i < 64; i += THREADS) { sb1[i] = bi[i]; sb2[i] = b1[i]; sb3[i] = b2[i]; }
    if (tid < 16) sb4[tid] = bo[tid];
    __syncthreads();

    const int wstride = gridDim.x * WARPS;
    for (int wt = blockIdx.x * WARPS + wid; wt < WTILES; wt += wstride) {
        const size_t rowbase = (size_t)wt * 64;

        // ---- load x (64x32) -> fp16 A frags, 4 subtiles ----
        uint32_t A[4][16];
#pragma unroll
        for (int st = 0; st < 4; st++) {
            const float* xr0 = x + (rowbase + st * 16 + g) * 32;
            const float* xr8 = x + (rowbase + st * 16 + g + 8) * 32;
#pragma unroll
            for (int ks = 0; ks < 2; ks++) {
                float2 v0 = *(const float2*)&xr0[ks * 16 + 2 * t];
                float2 v1 = *(const float2*)&xr8[ks * 16 + 2 * t];
                float2 v2 = *(const float2*)&xr0[ks * 16 + 8 + 2 * t];
                float2 v3 = *(const float2*)&xr8[ks * 16 + 8 + 2 * t];
                A[st][ks * 4 + 0] = pack_h(v0.x, v0.y);
                A[st][ks * 4 + 1] = pack_h(v1.x, v1.y);
                A[st][ks * 4 + 2] = pack_h(v2.x, v2.y);
                A[st][ks * 4 + 3] = pack_h(v3.x, v3.y);
            }
        }

        float d[4][8][4];

        // ---- L1: 32 -> 64 ----
        layer_mma4<2, 8>(d, sf1, A, lane);
#pragma unroll
        for (int st = 0; st < 4; st++) epi_relu(d[st], sb1, lane, A[st]);

        // ---- L2: 64 -> 64 ----
        layer_mma4<4, 8>(d, sf2, A, lane);
#pragma unroll
        for (int st = 0; st < 4; st++) epi_relu(d[st], sb2, lane, A[st]);

        // ---- L3: 64 -> 64 ----
        layer_mma4<4, 8>(d, sf3, A, lane);
#pragma unroll
        for (int st = 0; st < 4; st++) epi_relu(d[st], sb3, lane, A[st]);

        // ---- L4: 64 -> 16 (no relu) ----
        float e4[4][2][4];
        layer_mma4<4, 2>(e4, sf4, A, lane);

        // ---- store all 4 subtiles ----
#pragma unroll
        for (int st = 0; st < 4; st++) {
            float* o0 = out + (rowbase + st * 16 + g) * 16;
            float* o8 = out + (rowbase + st * 16 + g + 8) * 16;
#pragma unroll
            for (int j = 0; j < 2; j++) {
                float2 b = *(const float2*)&sb4[j * 8 + 2 * t];
                *(float2*)&o0[j * 8 + 2 * t] = make_float2(e4[st][j][0] + b.x, e4[st][j][1] + b.y);
                *(float2*)&o8[j * 8 + 2 * t] = make_float2(e4[st][j][2] + b.x, e4[st][j][3] + b.y);
            }
        }
    }
}

extern "C" void kernel_launch(void* const* d_in, const int* in_sizes, int n_in,
                              void* d_out, int out_size) {
    (void)in_sizes; (void)n_in; (void)out_size;
    const float* x  = (const float*)d_in[0];
    const float* Wi = (const float*)d_in[1];
    const float* bi = (const float*)d_in[2];
    const float* W1 = (const float*)d_in[3];
    const float* b1 = (const float*)d_in[4];
    const float* W2 = (const float*)d_in[5];
    const float* b2 = (const float*)d_in[6];
    const float* Wo = (const float*)d_in[7];
    const float* bo = (const float*)d_in[8];
    float* out = (float*)d_out;

    mlp_hmma_kernel<<<GRID, THREADS>>>(x, Wi, bi, W1, b1, W2, b2, Wo, bo, out);
}

// round 15
// speedup vs baseline: 1.0464x; 1.0464x over previous
#include <cuda_runtime.h>
#include <cuda_fp16.h>
#include <cstdint>

// InstantNGPMLP fused on mma.sync m16n8k16 (tcgen05 unavailable under the
// harness's compute_103 virtual arch).
// R15 vs R13 (77.9us best, M=32 @ 12 warps/SM, L1=61.4%, tensor=50.9%)
//     and R14 (86.5us, M=64 @ 8 warps — warp-starved):
//   - SAME M=32 compute structure, THINNER registers -> 16 warps/SM:
//     * raw-x prefetch buffer dropped (-32 regs; 16 warps hide x latency)
//     * per-j B loads instead of banked b[8] (-14 regs)
//     * zero-C mma for ks=0 (no accumulator-init MOVs)
//   - launch_bounds(128,4): ~118 live regs < 128 cap, grid 592.
//   - pure fp16 operands (rel_err 2.984e-4, 3.3x margin).

#define THREADS 128
#define WARPS 4
#define NROWS 1048576
#define WTILES (NROWS / 32)   // 32768 warp-tiles of 32 rows
#define GRID 592              // 4 CTAs/SM * 148

__device__ __forceinline__ void mma16816(float d[4], const uint32_t* a, uint32_t b0, uint32_t b1) {
    asm volatile(
        "mma.sync.aligned.m16n8k16.row.col.f32.f16.f16.f32 "
        "{%0,%1,%2,%3}, {%4,%5,%6,%7}, {%8,%9}, {%0,%1,%2,%3};"
        : "+f"(d[0]), "+f"(d[1]), "+f"(d[2]), "+f"(d[3])
        : "r"(a[0]), "r"(a[1]), "r"(a[2]), "r"(a[3]), "r"(b0), "r"(b1));
}
// Zero-C form: d = A*B (no accumulator pre-init).
__device__ __forceinline__ void mma16816_z(float d[4], const uint32_t* a, uint32_t b0, uint32_t b1) {
    asm volatile(
        "mma.sync.aligned.m16n8k16.row.col.f32.f16.f16.f32 "
        "{%0,%1,%2,%3}, {%4,%5,%6,%7}, {%8,%9}, {%10,%10,%10,%10};"
        : "=f"(d[0]), "=f"(d[1]), "=f"(d[2]), "=f"(d[3])
        : "r"(a[0]), "r"(a[1]), "r"(a[2]), "r"(a[3]), "r"(b0), "r"(b1), "f"(0.0f));
}

__device__ __forceinline__ uint32_t pack_h(float f0, float f1) {
    __half2 h = __floats2half2_rn(f0, f1);
    return *reinterpret_cast<uint32_t*>(&h);
}

// ---- smem: fp16 B fragments (~22KB) + biases ----
__shared__ uint2 sf1[512];    // L1: 2ks x 8nf x 32 lanes
__shared__ uint2 sf2[1024];   // L2: 4ks x 8nf x 32
__shared__ uint2 sf3[1024];   // L3
__shared__ uint2 sf4[256];    // L4: 4ks x 2nf x 32
__shared__ float sb1[64], sb2[64], sb3[64], sb4[16];

__device__ void stage(const float* __restrict__ W, int K, int N,
                      uint2* __restrict__ frag, int tid) {
    const int NF = N / 8, total = (K / 16) * NF * 32;
    for (int idx = tid; idx < total; idx += THREADS) {
        int lane = idx & 31, f = idx >> 5;
        int j = f % NF, ks = f / NF;
        int g = lane >> 2, t = lane & 3;
        int n = j * 8 + g;
        int k0 = ks * 16 + 2 * t;
        frag[idx] = make_uint2(pack_h(W[k0 * N + n],       W[(k0 + 1) * N + n]),
                               pack_h(W[(k0 + 8) * N + n], W[(k0 + 9) * N + n]));
    }
}

// Two-subtile layer, per-j B loads: one LDS feeds 2 mma; ks=0 uses zero-C.
template <int KS, int NF>
__device__ __forceinline__ void layer_mma2(float (&d0)[NF][4], float (&d1)[NF][4],
                                           const uint2* __restrict__ frag,
                                           const uint32_t* __restrict__ A0,
                                           const uint32_t* __restrict__ A1,
                                           int lane) {
#pragma unroll
    for (int ks = 0; ks < KS; ks++) {
#pragma unroll
        for (int j = 0; j < NF; j++) {
            uint2 b = frag[(ks * NF + j) * 32 + lane];
            if (ks == 0) {
                mma16816_z(d0[j], &A0[0], b.x, b.y);
                mma16816_z(d1[j], &A1[0], b.x, b.y);
            } else {
                mma16816(d0[j], &A0[ks * 4], b.x, b.y);
                mma16816(d1[j], &A1[ks * 4], b.x, b.y);
            }
        }
    }
}

// Epilogue: bias + relu + fp16 pack (one subtile).
__device__ __forceinline__ void epi_relu(const float (&d)[8][4],
                                         const float* __restrict__ bias, int lane,
                                         uint32_t* __restrict__ Ah) {
    int t = lane & 3;
#pragma unroll
    for (int ks = 0; ks < 4; ks++) {
#pragma unroll
        for (int h = 0; h < 2; h++) {
            int j = 2 * ks + h;
            float2 b = *(const float2*)&bias[j * 8 + 2 * t];
            float f0 = fmaxf(d[j][0] + b.x, 0.0f);
            float f1 = fmaxf(d[j][1] + b.y, 0.0f);
            float f2 = fmaxf(d[j][2] + b.x, 0.0f);
            float f3 = fmaxf(d[j][3] + b.y, 0.0f);
            Ah[ks * 4 + h * 2 + 0] = pack_h(f0, f1);
            Ah[ks * 4 + h * 2 + 1] = pack_h(f2, f3);
        }
    }
}

__global__ void __launch_bounds__(THREADS, 4)
mlp_hmma_kernel(const float* __restrict__ x,
                const float* __restrict__ Wi, const float* __restrict__ bi,
                const float* __restrict__ W1, const float* __restrict__ b1,
                const float* __restrict__ W2, const float* __restrict__ b2,
                const float* __restrict__ Wo, const float* __restrict__ bo,
                float* __restrict__ out) {
    const int tid = threadIdx.x;
    const int wid = tid >> 5;
    const int lane = tid & 31;
    const int g = lane >> 2, t = lane & 3;

    stage(Wi, 32, 64, sf1, tid);
    stage(W1, 64, 64, sf2, tid);
    stage(W2, 64, 64, sf3, tid);
    stage(Wo, 64, 16, sf4, tid);
    for (int i = tid; i < 64; i += THREADS) { sb1[i] = bi[i]; sb2[i] = b1[i]; sb3[i] = b2[i]; }
    if (tid < 16) sb4[tid] = bo[tid];
    __syncthreads();

    const int wstride = gridDim.x * WARPS;
    for (int wt = blockIdx.x * WARPS + wid; wt < WTILES; wt += wstride) {
        const size_t rowbase = (size_t)wt * 32;

        // ---- load x (32x32) -> fp16 A frags, 2 subtiles ----
        uint32_t A0[16], A1[16];
#pragma unroll
        for (int st = 0; st < 2; st++) {
            uint32_t* A = st ? A1 : A0;
            const float* xr0 = x + (rowbase + st * 16 + g) * 32;
            const float* xr8 = x + (rowbase + st * 16 + g + 8) * 32;
#pragma unroll
            for (int ks = 0; ks < 2; ks++) {
                float2 v0 = *(const float2*)&xr0[ks * 16 + 2 * t];
                float2 v1 = *(const float2*)&xr8[ks * 16 + 2 * t];
                float2 v2 = *(const float2*)&xr0[ks * 16 + 8 + 2 * t];
                float2 v3 = *(const float2*)&xr8[ks * 16 + 8 + 2 * t];
                A[ks * 4 + 0] = pack_h(v0.x, v0.y);
                A[ks * 4 + 1] = pack_h(v1.x, v1.y);
                A[ks * 4 + 2] = pack_h(v2.x, v2.y);
                A[ks * 4 + 3] = pack_h(v3.x, v3.y);
            }
        }

        float d0[8][4], d1[8][4];

        // ---- L1: 32 -> 64 ----
        layer_mma2<2, 8>(d0, d1, sf1, A0, A1, lane);
        epi_relu(d0, sb1, lane, A0);
        epi_relu(d1, sb1, lane, A1);

        // ---- L2: 64 -> 64 ----
        layer_mma2<4, 8>(d0, d1, sf2, A0, A1, lane);
        epi_relu(d0, sb2, lane, A0);
        epi_relu(d1, sb2, lane, A1);

        // ---- L3: 64 -> 64 ----
        layer_mma2<4, 8>(d0, d1, sf3, A0, A1, lane);
        epi_relu(d0, sb3, lane, A0);
        epi_relu(d1, sb3, lane, A1);

        // ---- L4: 64 -> 16 (no relu) ----
        float e0[2][4], e1[2][4];
        layer_mma2<4, 2>(e0, e1, sf4, A0, A1, lane);

        // ---- store both subtiles ----
#pragma unroll
        for (int mt = 0; mt < 2; mt++) {
            const float (&dd)[2][4] = mt ? e1 : e0;
            float* o0 = out + (rowbase + mt * 16 + g) * 16;
            float* o8 = out + (rowbase + mt * 16 + g + 8) * 16;
#pragma unroll
            for (int j = 0; j < 2; j++) {
                float2 b = *(const float2*)&sb4[j * 8 + 2 * t];
                *(float2*)&o0[j * 8 + 2 * t] = make_float2(dd[j][0] + b.x, dd[j][1] + b.y);
                *(float2*)&o8[j * 8 + 2 * t] = make_float2(dd[j][2] + b.x, dd[j][3] + b.y);
            }
        }
    }
}

extern "C" void kernel_launch(void* const* d_in, const int* in_sizes, int n_in,
                              void* d_out, int out_size) {
    (void)in_sizes; (void)n_in; (void)out_size;
    const float* x  = (const float*)d_in[0];
    const float* Wi = (const float*)d_in[1];
    const float* bi = (const float*)d_in[2];
    const float* W1 = (const float*)d_in[3];
    const float* b1 = (const float*)d_in[4];
    const float* W2 = (const float*)d_in[5];
    const float* b2 = (const float*)d_in[6];
    const float* Wo = (const float*)d_in[7];
    const float* bo = (const float*)d_in[8];
    float* out = (float*)d_out;

    mlp_hmma_kernel<<<GRID, THREADS>>>(x, Wi, bi, W1, b1, W2, b2, Wo, bo, out);
}